// round 2
// baseline (speedup 1.0000x reference)
#include <cuda_runtime.h>
#include <math.h>

#define BB   64
#define TT   256
#define HH   1024
#define DIN  2144
#define AW   32
#define MTOT 16384          // B*T
#define NKC  8              // K-split chunks for GRU recurrent GEMM

// ---------------- scratch (device globals; allocation-free) ----------------
static __device__ float g_tmean[BB*HH];            // mean of txt_ctx over LTXT
static __device__ float g_xin [MTOT*DIN];          // concat input  (140 MB)
static __device__ float g_xf  [MTOT*HH];           // fused+gelu
static __device__ float g_gi  [MTOT*3*HH];         // x@Wih^T + bih (201 MB)
static __device__ float g_gru [MTOT*HH];           // GRU hidden per step
static __device__ float g_ghp [NKC*BB*3*HH];       // K-split partials of h@Whh^T
static __device__ float g_y   [MTOT*HH];           // adapter mid
static __device__ float g_x2  [MTOT*HH];           // adapter out
static __device__ float g_ha  [MTOT*HH];           // head mid
static __device__ float g_da  [MTOT*512];          // done mid

__device__ __forceinline__ float gelu_f(float x) {
    return 0.5f * x * (1.0f + erff(x * 0.70710678118654752f));
}
__device__ __forceinline__ float sigm_f(float x) {
    return 1.0f / (1.0f + expf(-x));
}

// ---------------- txt_ctx mean over LTXT ----------------
__global__ void tmean_k(const float* __restrict__ txt) {
    int b = blockIdx.x;
    for (int d = threadIdx.x; d < HH; d += blockDim.x) {
        float s = 0.f;
        #pragma unroll 4
        for (int l = 0; l < 64; l++)
            s += txt[((size_t)b * 64 + l) * HH + d];
        g_tmean[b * HH + d] = s * (1.0f / 64.0f);
    }
}

// ---------------- materialize concat input [MTOT, DIN] ----------------
__global__ void xin_k(const float* __restrict__ img, const float* __restrict__ st,
                      const float* __restrict__ emb, const int* __restrict__ skill) {
    int k = blockIdx.x * 256 + threadIdx.x;
    if (k >= DIN) return;
    int m = blockIdx.y;
    int b = m >> 8;
    float v;
    if (k < 1024)      v = g_tmean[b * HH + k];
    else if (k < 2048) v = img[(size_t)m * 1024 + (k - 1024)];
    else if (k < 2080) v = st [(size_t)m * 32   + (k - 2048)];
    else               v = emb[skill[b] * 64 + (k - 2080)];
    g_xin[(size_t)m * DIN + k] = v;
}

// ---------------- generic 128x128x16 SGEMM ----------------
// C[m,n] = act( sum_k A[m,k] * B(k,n) + bias[n] )
// BT=false: B row-major [K,N].  BT=true: B is [N,K] (B(k,n)=B[n*K+k]).
// ACT: 0=none, 1=gelu.  Batched via blockIdx.z (+ optional skill gather for B/bias).
template<int ACT, bool BT>
__global__ __launch_bounds__(256)
void gemm_k(const float* __restrict__ A, const float* __restrict__ B,
            const float* __restrict__ bias, float* __restrict__ C,
            int M, int N, int K, int ldc,
            long sA, long sB, long sC, long sBias, const int* __restrict__ skill)
{
    int z = blockIdx.z;
    if (skill) { long s = skill[z]; B += s * sB; bias += s * sBias; }
    A += (long)z * sA;  C += (long)z * sC;

    __shared__ float As[16][132];
    __shared__ float Bs[16][132];

    int tid = threadIdx.x;
    int m0 = blockIdx.y * 128;
    int n0 = blockIdx.x * 128;
    int tx = tid & 15, ty = tid >> 4;

    float acc[8][8];
    #pragma unroll
    for (int i = 0; i < 8; i++)
        #pragma unroll
        for (int j = 0; j < 8; j++) acc[i][j] = 0.f;

    int am  = tid >> 2;           // 0..63
    int akq = (tid & 3) << 2;     // 0,4,8,12
    int bk  = tid >> 5;           // 0..7  (non-BT B)
    int bn  = (tid & 31) << 2;    // 0..124

    for (int k0 = 0; k0 < K; k0 += 16) {
        // ---- load A tile (transposed into smem) ----
        #pragma unroll
        for (int r = 0; r < 2; r++) {
            int m = m0 + am + r * 64;
            float4 v = *(const float4*)(A + (long)m * K + k0 + akq);
            As[akq + 0][am + r * 64] = v.x;
            As[akq + 1][am + r * 64] = v.y;
            As[akq + 2][am + r * 64] = v.z;
            As[akq + 3][am + r * 64] = v.w;
        }
        // ---- load B tile ----
        if (BT) {
            #pragma unroll
            for (int r = 0; r < 2; r++) {
                int n = n0 + am + r * 64;
                if (n < N) {
                    float4 v = *(const float4*)(B + (long)n * K + k0 + akq);
                    Bs[akq + 0][am + r * 64] = v.x;
                    Bs[akq + 1][am + r * 64] = v.y;
                    Bs[akq + 2][am + r * 64] = v.z;
                    Bs[akq + 3][am + r * 64] = v.w;
                } else {
                    Bs[akq + 0][am + r * 64] = 0.f;
                    Bs[akq + 1][am + r * 64] = 0.f;
                    Bs[akq + 2][am + r * 64] = 0.f;
                    Bs[akq + 3][am + r * 64] = 0.f;
                }
            }
        } else {
            #pragma unroll
            for (int r = 0; r < 2; r++) {
                int kk = bk + r * 8;
                int n  = n0 + bn;
                const float* src = B + (long)(k0 + kk) * N + n;
                if (n + 3 < N) {
                    *(float4*)&Bs[kk][bn] = *(const float4*)src;
                } else {
                    #pragma unroll
                    for (int e = 0; e < 4; e++)
                        Bs[kk][bn + e] = (n + e < N) ? src[e] : 0.f;
                }
            }
        }
        __syncthreads();

        #pragma unroll
        for (int kk = 0; kk < 16; kk++) {
            float a[8], b[8];
            *(float4*)&a[0] = *(const float4*)&As[kk][ty * 8];
            *(float4*)&a[4] = *(const float4*)&As[kk][ty * 8 + 4];
            *(float4*)&b[0] = *(const float4*)&Bs[kk][tx * 8];
            *(float4*)&b[4] = *(const float4*)&Bs[kk][tx * 8 + 4];
            #pragma unroll
            for (int i = 0; i < 8; i++)
                #pragma unroll
                for (int j = 0; j < 8; j++)
                    acc[i][j] += a[i] * b[j];
        }
        __syncthreads();
    }

    #pragma unroll
    for (int i = 0; i < 8; i++) {
        int m = m0 + ty * 8 + i;
        #pragma unroll
        for (int j = 0; j < 8; j++) {
            int n = n0 + tx * 8 + j;
            if (n < N) {
                float v = acc[i][j] + bias[n];
                if (ACT == 1) v = gelu_f(v);
                C[(long)m * ldc + n] = v;
            }
        }
    }
}

// ---------------- GRU recurrent: K-split GEMM gh = h_{t-1} @ Whh^T ----------------
// grid (64 j-tiles of 16, NKC k-chunks), block 192 threads.
// Block computes partial[kc][b in 0..63][48 cols = 3 gates x 16 j].
__global__ __launch_bounds__(192)
void gru_gh_k(const float* __restrict__ Whh, int t)
{
    __shared__ float Hs[32][68];
    __shared__ float Ws[32][52];

    int tid = threadIdx.x;
    int jt  = blockIdx.x;
    int kc  = blockIdx.y;
    int j0  = jt * 16;
    const float* hp = g_gru + (size_t)(t - 1) * HH;   // + b*T*H + k

    int ty = tid & 15;    // b group (x4)
    int tx = tid >> 4;    // 0..11 col group (x4)

    float acc[4][4];
    #pragma unroll
    for (int i = 0; i < 4; i++)
        #pragma unroll
        for (int j = 0; j < 4; j++) acc[i][j] = 0.f;

    const int KCHUNK = HH / NKC;          // 128
    for (int kt = 0; kt < KCHUNK / 32; kt++) {
        int k0 = kc * KCHUNK + kt * 32;
        for (int idx = tid; idx < 64 * 32; idx += 192) {
            int b = idx >> 5, kk = idx & 31;
            Hs[kk][b] = hp[(size_t)b * TT * HH + k0 + kk];
        }
        for (int idx = tid; idx < 48 * 32; idx += 192) {
            int c = idx >> 5, kk = idx & 31;
            int row = (c >> 4) * HH + j0 + (c & 15);
            Ws[kk][c] = Whh[(size_t)row * HH + k0 + kk];
        }
        __syncthreads();
        #pragma unroll
        for (int kk = 0; kk < 32; kk++) {
            float h[4], w[4];
            *(float4*)h = *(const float4*)&Hs[kk][ty * 4];
            *(float4*)w = *(const float4*)&Ws[kk][tx * 4];
            #pragma unroll
            for (int i = 0; i < 4; i++)
                #pragma unroll
                for (int j = 0; j < 4; j++)
                    acc[i][j] += h[i] * w[j];
        }
        __syncthreads();
    }

    #pragma unroll
    for (int i = 0; i < 4; i++) {
        int b = ty * 4 + i;
        #pragma unroll
        for (int j = 0; j < 4; j++) {
            int c   = tx * 4 + j;
            int col = (c >> 4) * HH + j0 + (c & 15);
            g_ghp[((size_t)(kc * 64 + b)) * 3 * HH + col] = acc[i][j];
        }
    }
}

// ---------------- GRU gates + state update ----------------
__global__ void gru_gate_k(const float* __restrict__ bhh, int t)
{
    int b = blockIdx.x, j = threadIdx.x;
    float ghr = bhh[j], ghz = bhh[HH + j], ghn = bhh[2 * HH + j];
    float hprev = 0.f;
    if (t > 0) {
        hprev = g_gru[(size_t)b * TT * HH + (size_t)(t - 1) * HH + j];
        #pragma unroll
        for (int kc = 0; kc < NKC; kc++) {
            size_t base = ((size_t)(kc * 64 + b)) * 3 * HH;
            ghr += g_ghp[base + j];
            ghz += g_ghp[base + HH + j];
            ghn += g_ghp[base + 2 * HH + j];
        }
    }
    const float* gi = g_gi + (size_t)(b * TT + t) * 3 * HH;
    float r = sigm_f(gi[j] + ghr);
    float z = sigm_f(gi[HH + j] + ghz);
    float n = tanhf(gi[2 * HH + j] + r * ghn);
    g_gru[(size_t)b * TT * HH + (size_t)t * HH + j] = (1.f - z) * n + z * hprev;
}

// ---------------- done head second layer: warp-per-row dot + sigmoid ----------------
__global__ void done2_k(const float* __restrict__ W, const float* __restrict__ b2,
                        float* __restrict__ out)
{
    int w = threadIdx.x >> 5, lane = threadIdx.x & 31;
    int row = blockIdx.x * 8 + w;
    const float* x = g_da + (size_t)row * 512;
    float s = 0.f;
    #pragma unroll 4
    for (int k = lane; k < 512; k += 32) s += x[k] * W[k];
    #pragma unroll
    for (int o = 16; o; o >>= 1) s += __shfl_down_sync(0xffffffffu, s, o);
    if (lane == 0) out[MTOT * AW + row] = sigm_f(s + b2[0]);
}

// ---------------- launch ----------------
extern "C" void kernel_launch(void* const* d_in, const int* in_sizes, int n_in,
                              void* d_out, int out_size)
{
    const float* txt = (const float*)d_in[0];
    const float* img = (const float*)d_in[1];
    const float* st  = (const float*)d_in[2];
    const int*   skl = (const int*)  d_in[3];
    const float* emb = (const float*)d_in[4];
    const float* fW  = (const float*)d_in[5];
    const float* fb  = (const float*)d_in[6];
    const float* Wih = (const float*)d_in[7];
    const float* Whh = (const float*)d_in[8];
    const float* bih = (const float*)d_in[9];
    const float* bhh = (const float*)d_in[10];
    const float* aW1 = (const float*)d_in[11];
    const float* ab1 = (const float*)d_in[12];
    const float* aW2 = (const float*)d_in[13];
    const float* ab2 = (const float*)d_in[14];
    const float* hW1 = (const float*)d_in[15];
    const float* hb1 = (const float*)d_in[16];
    const float* hW2 = (const float*)d_in[17];
    const float* hb2 = (const float*)d_in[18];
    const float* dW1 = (const float*)d_in[19];
    const float* db1 = (const float*)d_in[20];
    const float* dW2 = (const float*)d_in[21];
    const float* db2 = (const float*)d_in[22];
    float* out = (float*)d_out;

    float *p_xin, *p_xf, *p_gi, *p_gru, *p_y, *p_x2, *p_ha, *p_da;
    cudaGetSymbolAddress((void**)&p_xin, g_xin);
    cudaGetSymbolAddress((void**)&p_xf,  g_xf);
    cudaGetSymbolAddress((void**)&p_gi,  g_gi);
    cudaGetSymbolAddress((void**)&p_gru, g_gru);
    cudaGetSymbolAddress((void**)&p_y,   g_y);
    cudaGetSymbolAddress((void**)&p_x2,  g_x2);
    cudaGetSymbolAddress((void**)&p_ha,  g_ha);
    cudaGetSymbolAddress((void**)&p_da,  g_da);

    // 1) txt mean + concat input
    tmean_k<<<BB, 256>>>(txt);
    xin_k<<<dim3((DIN + 255) / 256, MTOT), 256>>>(img, st, emb, skl);

    // 2) fuse GEMM + gelu:  [16384,2144] @ [2144,1024]
    gemm_k<1, false><<<dim3(HH / 128, MTOT / 128, 1), 256>>>(
        p_xin, fW, fb, p_xf, MTOT, HH, DIN, HH, 0, 0, 0, 0, nullptr);

    // 3) GRU input projection: gi = x @ Wih^T + bih  (Wih is [3H,H] -> BT)
    gemm_k<0, true><<<dim3(3 * HH / 128, MTOT / 128, 1), 256>>>(
        p_xf, Wih, bih, p_gi, MTOT, 3 * HH, HH, 3 * HH, 0, 0, 0, 0, nullptr);

    // 4) GRU recurrence: 256 sequential steps
    for (int t = 0; t < TT; t++) {
        if (t > 0) gru_gh_k<<<dim3(64, NKC), 192>>>(Whh, t);
        gru_gate_k<<<BB, HH>>>(bhh, t);
    }

    // 5) per-skill adapter (batched GEMMs over blockIdx.z = b)
    gemm_k<1, false><<<dim3(HH / 128, 2, BB), 256>>>(
        p_gru, aW1, ab1, p_y, TT, HH, HH, HH,
        (long)TT * HH, (long)HH * HH, (long)TT * HH, HH, skl);
    gemm_k<0, false><<<dim3(HH / 128, 2, BB), 256>>>(
        p_y, aW2, ab2, p_x2, TT, HH, HH, HH,
        (long)TT * HH, (long)HH * HH, (long)TT * HH, HH, skl);

    // 6) action head
    gemm_k<1, false><<<dim3(HH / 128, MTOT / 128, 1), 256>>>(
        p_x2, hW1, hb1, p_ha, MTOT, HH, HH, HH, 0, 0, 0, 0, nullptr);
    gemm_k<0, false><<<dim3(1, MTOT / 128, 1), 256>>>(
        p_ha, hW2, hb2, out, MTOT, AW, HH, AW, 0, 0, 0, 0, nullptr);

    // 7) done head
    gemm_k<1, false><<<dim3(512 / 128, MTOT / 128, 1), 256>>>(
        p_x2, dW1, db1, p_da, MTOT, 512, HH, 512, 0, 0, 0, 0, nullptr);
    done2_k<<<MTOT / 8, 256>>>(dW2, db2, out);
}

// round 4
// speedup vs baseline: 1.5847x; 1.5847x over previous
#include <cuda_runtime.h>
#include <math.h>
#include <stdint.h>

#define BB   64
#define TT   256
#define HH   1024
#define DIN  2144
#define AW   32
#define MTOT 16384
#define NKC  8

// ---------------- scratch ----------------
static __device__ float g_tmean[BB*HH];
static __device__ float g_xin [MTOT*DIN];
static __device__ float g_xf  [MTOT*HH];
static __device__ float g_gi  [MTOT*3*HH];
static __device__ float g_gru [MTOT*HH];
static __device__ float g_ghp [NKC*BB*3*HH];
static __device__ float g_y   [MTOT*HH];
static __device__ float g_x2  [MTOT*HH];
static __device__ float g_ha  [MTOT*HH];
static __device__ float g_da  [MTOT*512];
// transposed weights ([N][K] layout for the GEMM B operand)
static __device__ float g_fWT [HH*DIN];
static __device__ float g_aW1T[9*HH*HH];
static __device__ float g_aW2T[9*HH*HH];
static __device__ float g_hW1T[HH*HH];
static __device__ float g_dW1T[512*HH];

__device__ __forceinline__ float gelu_f(float x) {
    return 0.5f * x * (1.0f + erff(x * 0.70710678118654752f));
}
__device__ __forceinline__ float sigm_f(float x) {
    return 1.0f / (1.0f + expf(-x));
}
__device__ __forceinline__ float tf32r(float x) {
    uint32_t u;
    asm("cvt.rna.tf32.f32 %0, %1;" : "=r"(u) : "f"(x));
    return __uint_as_float(u);
}

// ---------------- tf32 mma.sync GEMM: C = act(A[M,K] @ Bt[N,K]^T + bias) ----------------
// Block 128x128, K-chunk 32, 8 warps (2x4), warp tile 64x32, m16n8k8 fragments.
#define PITCH 36
#define SLOTF (128 * PITCH)
static constexpr int MG_SMEM = 2 * 2 * SLOTF * 4;   // 73728 bytes

template<int ACT>
__global__ __launch_bounds__(256)
void mma_gemm(const float* __restrict__ A, const float* __restrict__ Bt,
              const float* __restrict__ bias, float* __restrict__ C,
              int K, int ldc, long sA, long sB, long sC, long sBias,
              const int* __restrict__ skill)
{
    extern __shared__ float sm[];
    float* As = sm;                 // [2][128][PITCH]
    float* Bs = sm + 2 * SLOTF;     // [2][128][PITCH]

    int z = blockIdx.z;
    if (skill) { long s = skill[z]; Bt += s * sB; bias += s * sBias; }
    A += (long)z * sA;  C += (long)z * sC;

    int tid = threadIdx.x, wid = tid >> 5, lane = tid & 31;
    int wm = wid >> 2, wn = wid & 3;          // warp grid 2 x 4
    int g  = lane >> 2, t4 = lane & 3;
    long m0 = (long)blockIdx.y * 128, n0 = (long)blockIdx.x * 128;

    int rowq[4], segq[4];
    #pragma unroll
    for (int j = 0; j < 4; j++) { int q = tid + j * 256; rowq[j] = q >> 3; segq[j] = q & 7; }

    const int NC = K / 32;

    // prologue: chunk 0 -> slot 0
    #pragma unroll
    for (int j = 0; j < 4; j++) {
        float4 va = *(const float4*)(A  + (m0 + rowq[j]) * K + segq[j] * 4);
        float4 vb = *(const float4*)(Bt + (n0 + rowq[j]) * K + segq[j] * 4);
        va.x = tf32r(va.x); va.y = tf32r(va.y); va.z = tf32r(va.z); va.w = tf32r(va.w);
        vb.x = tf32r(vb.x); vb.y = tf32r(vb.y); vb.z = tf32r(vb.z); vb.w = tf32r(vb.w);
        *(float4*)(As + rowq[j] * PITCH + segq[j] * 4) = va;
        *(float4*)(Bs + rowq[j] * PITCH + segq[j] * 4) = vb;
    }
    __syncthreads();

    float acc[4][4][4];
    #pragma unroll
    for (int mf = 0; mf < 4; mf++)
        #pragma unroll
        for (int nf = 0; nf < 4; nf++)
            #pragma unroll
            for (int e = 0; e < 4; e++) acc[mf][nf][e] = 0.f;

    for (int i = 0; i < NC; i++) {
        int s = i & 1;
        float4 ra[4], rb[4];
        if (i + 1 < NC) {
            long k0 = (long)(i + 1) * 32;
            #pragma unroll
            for (int j = 0; j < 4; j++) {
                ra[j] = *(const float4*)(A  + (m0 + rowq[j]) * K + k0 + segq[j] * 4);
                rb[j] = *(const float4*)(Bt + (n0 + rowq[j]) * K + k0 + segq[j] * 4);
            }
        }

        const float* Ab = As + s * SLOTF + (wm * 64 + g) * PITCH + t4;
        const float* Bb = Bs + s * SLOTF + (wn * 32 + g) * PITCH + t4;
        #pragma unroll
        for (int ks = 0; ks < 4; ks++) {
            int kc = ks * 8;
            uint32_t af[4][4], bf[4][2];
            #pragma unroll
            for (int mf = 0; mf < 4; mf++) {
                const float* ap = Ab + mf * 16 * PITCH + kc;
                af[mf][0] = __float_as_uint(ap[0]);
                af[mf][1] = __float_as_uint(ap[8 * PITCH]);
                af[mf][2] = __float_as_uint(ap[4]);
                af[mf][3] = __float_as_uint(ap[8 * PITCH + 4]);
            }
            #pragma unroll
            for (int nf = 0; nf < 4; nf++) {
                const float* bp = Bb + nf * 8 * PITCH + kc;
                bf[nf][0] = __float_as_uint(bp[0]);
                bf[nf][1] = __float_as_uint(bp[4]);
            }
            #pragma unroll
            for (int mf = 0; mf < 4; mf++)
                #pragma unroll
                for (int nf = 0; nf < 4; nf++) {
                    asm("mma.sync.aligned.m16n8k8.row.col.f32.tf32.tf32.f32 "
                        "{%0,%1,%2,%3}, {%4,%5,%6,%7}, {%8,%9}, {%0,%1,%2,%3};"
                        : "+f"(acc[mf][nf][0]), "+f"(acc[mf][nf][1]),
                          "+f"(acc[mf][nf][2]), "+f"(acc[mf][nf][3])
                        : "r"(af[mf][0]), "r"(af[mf][1]), "r"(af[mf][2]), "r"(af[mf][3]),
                          "r"(bf[nf][0]), "r"(bf[nf][1]));
                }
        }

        if (i + 1 < NC) {
            int ns = (i + 1) & 1;
            #pragma unroll
            for (int j = 0; j < 4; j++) {
                float4 va = ra[j], vb = rb[j];
                va.x = tf32r(va.x); va.y = tf32r(va.y); va.z = tf32r(va.z); va.w = tf32r(va.w);
                vb.x = tf32r(vb.x); vb.y = tf32r(vb.y); vb.z = tf32r(vb.z); vb.w = tf32r(vb.w);
                *(float4*)(As + ns * SLOTF + rowq[j] * PITCH + segq[j] * 4) = va;
                *(float4*)(Bs + ns * SLOTF + rowq[j] * PITCH + segq[j] * 4) = vb;
            }
        }
        __syncthreads();
    }

    // epilogue: bias + optional gelu; float2 stores (c0,c1 are adjacent columns)
    #pragma unroll
    for (int mf = 0; mf < 4; mf++) {
        long mA = m0 + wm * 64 + mf * 16 + g;
        long mB = mA + 8;
        #pragma unroll
        for (int nf = 0; nf < 4; nf++) {
            long n = n0 + wn * 32 + nf * 8 + t4 * 2;
            float b0 = bias[n], b1 = bias[n + 1];
            float2 o0, o1;
            o0.x = acc[mf][nf][0] + b0; o0.y = acc[mf][nf][1] + b1;
            o1.x = acc[mf][nf][2] + b0; o1.y = acc[mf][nf][3] + b1;
            if (ACT == 1) {
                o0.x = gelu_f(o0.x); o0.y = gelu_f(o0.y);
                o1.x = gelu_f(o1.x); o1.y = gelu_f(o1.y);
            }
            *(float2*)(C + mA * ldc + n) = o0;
            *(float2*)(C + mB * ldc + n) = o1;
        }
    }
}

// ---------------- transpose: dst[C][R] = src[R][C] ----------------
__global__ void trans_k(const float* __restrict__ src, float* __restrict__ dst, int R, int Cc)
{
    __shared__ float t[32][33];
    long zoff = (long)blockIdx.z * R * Cc;
    int c0 = blockIdx.x * 32, r0 = blockIdx.y * 32;
    int x = threadIdx.x, y = threadIdx.y;
    #pragma unroll
    for (int dy = 0; dy < 32; dy += 8)
        t[y + dy][x] = src[zoff + (long)(r0 + y + dy) * Cc + c0 + x];
    __syncthreads();
    #pragma unroll
    for (int dy = 0; dy < 32; dy += 8)
        dst[zoff + (long)(c0 + y + dy) * R + r0 + x] = t[x][y + dy];
}

// ---------------- txt mean ----------------
__global__ void tmean_k(const float* __restrict__ txt) {
    int b = blockIdx.x;
    for (int d = threadIdx.x; d < HH; d += blockDim.x) {
        float s = 0.f;
        #pragma unroll 4
        for (int l = 0; l < 64; l++)
            s += txt[((size_t)b * 64 + l) * HH + d];
        g_tmean[b * HH + d] = s * (1.0f / 64.0f);
    }
}

// ---------------- concat input ----------------
__global__ void xin_k(const float* __restrict__ img, const float* __restrict__ st,
                      const float* __restrict__ emb, const int* __restrict__ skill) {
    int k = blockIdx.x * 256 + threadIdx.x;
    if (k >= DIN) return;
    int m = blockIdx.y;
    int b = m >> 8;
    float v;
    if (k < 1024)      v = g_tmean[b * HH + k];
    else if (k < 2048) v = img[(size_t)m * 1024 + (k - 1024)];
    else if (k < 2080) v = st [(size_t)m * 32   + (k - 2048)];
    else               v = emb[skill[b] * 64 + (k - 2080)];
    g_xin[(size_t)m * DIN + k] = v;
}

// ---------------- fallback fp32 SGEMM (head2 only) ----------------
template<int ACT, bool BT>
__global__ __launch_bounds__(256)
void gemm_k(const float* __restrict__ A, const float* __restrict__ B,
            const float* __restrict__ bias, float* __restrict__ C,
            int M, int N, int K, int ldc,
            long sA, long sB, long sC, long sBias, const int* __restrict__ skill)
{
    int z = blockIdx.z;
    if (skill) { long s = skill[z]; B += s * sB; bias += s * sBias; }
    A += (long)z * sA;  C += (long)z * sC;

    __shared__ float As[16][132];
    __shared__ float Bs[16][132];

    int tid = threadIdx.x;
    int m0 = blockIdx.y * 128;
    int n0 = blockIdx.x * 128;
    int tx = tid & 15, ty = tid >> 4;

    float acc[8][8];
    #pragma unroll
    for (int i = 0; i < 8; i++)
        #pragma unroll
        for (int j = 0; j < 8; j++) acc[i][j] = 0.f;

    int am  = tid >> 2;
    int akq = (tid & 3) << 2;
    int bk  = tid >> 5;
    int bn  = (tid & 31) << 2;

    for (int k0 = 0; k0 < K; k0 += 16) {
        #pragma unroll
        for (int r = 0; r < 2; r++) {
            int m = m0 + am + r * 64;
            float4 v = *(const float4*)(A + (long)m * K + k0 + akq);
            As[akq + 0][am + r * 64] = v.x;
            As[akq + 1][am + r * 64] = v.y;
            As[akq + 2][am + r * 64] = v.z;
            As[akq + 3][am + r * 64] = v.w;
        }
        if (BT) {
            #pragma unroll
            for (int r = 0; r < 2; r++) {
                int n = n0 + am + r * 64;
                if (n < N) {
                    float4 v = *(const float4*)(B + (long)n * K + k0 + akq);
                    Bs[akq + 0][am + r * 64] = v.x;
                    Bs[akq + 1][am + r * 64] = v.y;
                    Bs[akq + 2][am + r * 64] = v.z;
                    Bs[akq + 3][am + r * 64] = v.w;
                } else {
                    Bs[akq + 0][am + r * 64] = 0.f;
                    Bs[akq + 1][am + r * 64] = 0.f;
                    Bs[akq + 2][am + r * 64] = 0.f;
                    Bs[akq + 3][am + r * 64] = 0.f;
                }
            }
        } else {
            #pragma unroll
            for (int r = 0; r < 2; r++) {
                int kk = bk + r * 8;
                int n  = n0 + bn;
                const float* src = B + (long)(k0 + kk) * N + n;
                if (n + 3 < N) {
                    *(float4*)&Bs[kk][bn] = *(const float4*)src;
                } else {
                    #pragma unroll
                    for (int e = 0; e < 4; e++)
                        Bs[kk][bn + e] = (n + e < N) ? src[e] : 0.f;
                }
            }
        }
        __syncthreads();

        #pragma unroll
        for (int kk = 0; kk < 16; kk++) {
            float a[8], b[8];
            *(float4*)&a[0] = *(const float4*)&As[kk][ty * 8];
            *(float4*)&a[4] = *(const float4*)&As[kk][ty * 8 + 4];
            *(float4*)&b[0] = *(const float4*)&Bs[kk][tx * 8];
            *(float4*)&b[4] = *(const float4*)&Bs[kk][tx * 8 + 4];
            #pragma unroll
            for (int i = 0; i < 8; i++)
                #pragma unroll
                for (int j = 0; j < 8; j++)
                    acc[i][j] += a[i] * b[j];
        }
        __syncthreads();
    }

    #pragma unroll
    for (int i = 0; i < 8; i++) {
        int m = m0 + ty * 8 + i;
        #pragma unroll
        for (int j = 0; j < 8; j++) {
            int n = n0 + tx * 8 + j;
            if (n < N) {
                float v = acc[i][j] + bias[n];
                if (ACT == 1) v = gelu_f(v);
                C[(long)m * ldc + n] = v;
            }
        }
    }
}

// ---------------- GRU recurrent GEMM (K-split) ----------------
__global__ __launch_bounds__(192)
void gru_gh_k(const float* __restrict__ Whh, int t)
{
    __shared__ float Hs[32][68];
    __shared__ float Ws[32][52];

    int tid = threadIdx.x;
    int jt  = blockIdx.x;
    int kc  = blockIdx.y;
    int j0  = jt * 16;
    const float* hp = g_gru + (size_t)(t - 1) * HH;

    int ty = tid & 15;
    int tx = tid >> 4;

    float acc[4][4];
    #pragma unroll
    for (int i = 0; i < 4; i++)
        #pragma unroll
        for (int j = 0; j < 4; j++) acc[i][j] = 0.f;

    const int KCHUNK = HH / NKC;
    for (int kt = 0; kt < KCHUNK / 32; kt++) {
        int k0 = kc * KCHUNK + kt * 32;
        for (int idx = tid; idx < 64 * 32; idx += 192) {
            int b = idx >> 5, kk = idx & 31;
            Hs[kk][b] = hp[(size_t)b * TT * HH + k0 + kk];
        }
        for (int idx = tid; idx < 48 * 32; idx += 192) {
            int c = idx >> 5, kk = idx & 31;
            int row = (c >> 4) * HH + j0 + (c & 15);
            Ws[kk][c] = Whh[(size_t)row * HH + k0 + kk];
        }
        __syncthreads();
        #pragma unroll
        for (int kk = 0; kk < 32; kk++) {
            float h[4], w[4];
            *(float4*)h = *(const float4*)&Hs[kk][ty * 4];
            *(float4*)w = *(const float4*)&Ws[kk][tx * 4];
            #pragma unroll
            for (int i = 0; i < 4; i++)
                #pragma unroll
                for (int j = 0; j < 4; j++)
                    acc[i][j] += h[i] * w[j];
        }
        __syncthreads();
    }

    #pragma unroll
    for (int i = 0; i < 4; i++) {
        int b = ty * 4 + i;
        #pragma unroll
        for (int j = 0; j < 4; j++) {
            int c   = tx * 4 + j;
            int col = (c >> 4) * HH + j0 + (c & 15);
            g_ghp[((size_t)(kc * 64 + b)) * 3 * HH + col] = acc[i][j];
        }
    }
}

__global__ void gru_gate_k(const float* __restrict__ bhh, int t)
{
    int b = blockIdx.x, j = threadIdx.x;
    float ghr = bhh[j], ghz = bhh[HH + j], ghn = bhh[2 * HH + j];
    float hprev = 0.f;
    if (t > 0) {
        hprev = g_gru[(size_t)b * TT * HH + (size_t)(t - 1) * HH + j];
        #pragma unroll
        for (int kc = 0; kc < NKC; kc++) {
            size_t base = ((size_t)(kc * 64 + b)) * 3 * HH;
            ghr += g_ghp[base + j];
            ghz += g_ghp[base + HH + j];
            ghn += g_ghp[base + 2 * HH + j];
        }
    }
    const float* gi = g_gi + (size_t)(b * TT + t) * 3 * HH;
    float r = sigm_f(gi[j] + ghr);
    float z = sigm_f(gi[HH + j] + ghz);
    float n = tanhf(gi[2 * HH + j] + r * ghn);
    g_gru[(size_t)b * TT * HH + (size_t)t * HH + j] = (1.f - z) * n + z * hprev;
}

// ---------------- done head layer 2 ----------------
__global__ void done2_k(const float* __restrict__ W, const float* __restrict__ b2,
                        float* __restrict__ out)
{
    int w = threadIdx.x >> 5, lane = threadIdx.x & 31;
    int row = blockIdx.x * 8 + w;
    const float* x = g_da + (size_t)row * 512;
    float s = 0.f;
    #pragma unroll 4
    for (int k = lane; k < 512; k += 32) s += x[k] * W[k];
    #pragma unroll
    for (int o = 16; o; o >>= 1) s += __shfl_down_sync(0xffffffffu, s, o);
    if (lane == 0) out[MTOT * AW + row] = sigm_f(s + b2[0]);
}

// ---------------- launch ----------------
extern "C" void kernel_launch(void* const* d_in, const int* in_sizes, int n_in,
                              void* d_out, int out_size)
{
    const float* txt = (const float*)d_in[0];
    const float* img = (const float*)d_in[1];
    const float* st  = (const float*)d_in[2];
    const int*   skl = (const int*)  d_in[3];
    const float* emb = (const float*)d_in[4];
    const float* fW  = (const float*)d_in[5];
    const float* fb  = (const float*)d_in[6];
    const float* Wih = (const float*)d_in[7];
    const float* Whh = (const float*)d_in[8];
    const float* bih = (const float*)d_in[9];
    const float* bhh = (const float*)d_in[10];
    const float* aW1 = (const float*)d_in[11];
    const float* ab1 = (const float*)d_in[12];
    const float* aW2 = (const float*)d_in[13];
    const float* ab2 = (const float*)d_in[14];
    const float* hW1 = (const float*)d_in[15];
    const float* hb1 = (const float*)d_in[16];
    const float* hW2 = (const float*)d_in[17];
    const float* hb2 = (const float*)d_in[18];
    const float* dW1 = (const float*)d_in[19];
    const float* db1 = (const float*)d_in[20];
    const float* dW2 = (const float*)d_in[21];
    const float* db2 = (const float*)d_in[22];
    float* out = (float*)d_out;

    float *p_xin, *p_xf, *p_gi, *p_gru, *p_y, *p_x2, *p_ha, *p_da;
    float *p_fWT, *p_aW1T, *p_aW2T, *p_hW1T, *p_dW1T;
    cudaGetSymbolAddress((void**)&p_xin,  g_xin);
    cudaGetSymbolAddress((void**)&p_xf,   g_xf);
    cudaGetSymbolAddress((void**)&p_gi,   g_gi);
    cudaGetSymbolAddress((void**)&p_gru,  g_gru);
    cudaGetSymbolAddress((void**)&p_y,    g_y);
    cudaGetSymbolAddress((void**)&p_x2,   g_x2);
    cudaGetSymbolAddress((void**)&p_ha,   g_ha);
    cudaGetSymbolAddress((void**)&p_da,   g_da);
    cudaGetSymbolAddress((void**)&p_fWT,  g_fWT);
    cudaGetSymbolAddress((void**)&p_aW1T, g_aW1T);
    cudaGetSymbolAddress((void**)&p_aW2T, g_aW2T);
    cudaGetSymbolAddress((void**)&p_hW1T, g_hW1T);
    cudaGetSymbolAddress((void**)&p_dW1T, g_dW1T);

    cudaFuncSetAttribute(mma_gemm<0>, cudaFuncAttributeMaxDynamicSharedMemorySize, MG_SMEM);
    cudaFuncSetAttribute(mma_gemm<1>, cudaFuncAttributeMaxDynamicSharedMemorySize, MG_SMEM);

    // 0) weight transposes into [N][K]
    trans_k<<<dim3(32, 67), dim3(32, 8)>>>(fW,  p_fWT,  DIN, HH);
    trans_k<<<dim3(32, 32, 9), dim3(32, 8)>>>(aW1, p_aW1T, HH, HH);
    trans_k<<<dim3(32, 32, 9), dim3(32, 8)>>>(aW2, p_aW2T, HH, HH);
    trans_k<<<dim3(32, 32), dim3(32, 8)>>>(hW1, p_hW1T, HH, HH);
    trans_k<<<dim3(16, 32), dim3(32, 8)>>>(dW1, p_dW1T, HH, 512);

    // 1) txt mean + concat input
    tmean_k<<<BB, 256>>>(txt);
    xin_k<<<dim3((DIN + 255) / 256, MTOT), 256>>>(img, st, emb, skl);

    // 2) fuse GEMM + gelu (tf32 mma.sync)
    mma_gemm<1><<<dim3(HH / 128, MTOT / 128, 1), 256, MG_SMEM>>>(
        p_xin, p_fWT, fb, p_xf, DIN, HH, 0, 0, 0, 0, nullptr);

    // 3) GRU input projection (Wih already [3H,H])
    mma_gemm<0><<<dim3(3 * HH / 128, MTOT / 128, 1), 256, MG_SMEM>>>(
        p_xf, Wih, bih, p_gi, HH, 3 * HH, 0, 0, 0, 0, nullptr);

    // 4) GRU recurrence (fp32, unchanged)
    for (int t = 0; t < TT; t++) {
        if (t > 0) gru_gh_k<<<dim3(64, NKC), 192>>>(Whh, t);
        gru_gate_k<<<BB, HH>>>(bhh, t);
    }

    // 5) per-skill adapter (tf32, batched by skill)
    mma_gemm<1><<<dim3(HH / 128, TT / 128, BB), 256, MG_SMEM>>>(
        p_gru, p_aW1T, ab1, p_y, HH, HH,
        (long)TT * HH, (long)HH * HH, (long)TT * HH, HH, skl);
    mma_gemm<0><<<dim3(HH / 128, TT / 128, BB), 256, MG_SMEM>>>(
        p_y, p_aW2T, ab2, p_x2, HH, HH,
        (long)TT * HH, (long)HH * HH, (long)TT * HH, HH, skl);

    // 6) action head
    mma_gemm<1><<<dim3(HH / 128, MTOT / 128, 1), 256, MG_SMEM>>>(
        p_x2, p_hW1T, hb1, p_ha, HH, HH, 0, 0, 0, 0, nullptr);
    gemm_k<0, false><<<dim3(1, MTOT / 128, 1), 256>>>(
        p_ha, hW2, hb2, out, MTOT, AW, HH, AW, 0, 0, 0, 0, nullptr);

    // 7) done head
    mma_gemm<1><<<dim3(512 / 128, MTOT / 128, 1), 256, MG_SMEM>>>(
        p_x2, p_dW1T, db1, p_da, HH, 512, 0, 0, 0, 0, nullptr);
    done2_k<<<MTOT / 8, 256>>>(dW2, db2, out);
}